// round 1
// baseline (speedup 1.0000x reference)
#include <cuda_runtime.h>
#include <cstdint>
#include <cstddef>

#define FULLMASK 0xffffffffu

constexpr int Bx    = 2;
constexpr int Npt   = 20000;
constexpr int Cdim  = 256;
constexpr int Kn    = 16;
constexpr int Hdim  = 128;
constexpr int Mrows = Bx * Npt;   // 40000

// ---------------- scratch (device globals: allocation-free) ----------------
__device__ float g_Q[(size_t)3 * Mrows * Cdim];
__device__ float g_K[(size_t)3 * Mrows * Cdim];
__device__ float g_V[(size_t)3 * Mrows * Cdim];
__device__ float g_H[(size_t)Mrows * Hdim];
__device__ float g_alpha[(size_t)Mrows * 3];

// ---------------- tf32 GEMM:  C[M,N] = A[M,256] @ W[N,256]^T + bias --------
struct GemmJob {
    const float* A;
    const float* W;
    const float* bias;
    float*       C;
    int          ncols;
    int          relu;
};
struct GemmJobs { GemmJob j[10]; };

constexpr int BM = 64, BN = 64, BK = 32;
constexpr int KTILES = Cdim / BK;   // 8

__device__ __forceinline__ unsigned f2tf(float x) {
    unsigned r;
    asm("cvt.rna.tf32.f32 %0, %1;" : "=r"(r) : "f"(x));
    return r;
}

__device__ __forceinline__ void mma8(float c[4], const unsigned a[4], const unsigned b[2]) {
    asm volatile(
        "mma.sync.aligned.m16n8k8.row.col.f32.tf32.tf32.f32 "
        "{%0,%1,%2,%3}, {%4,%5,%6,%7}, {%8,%9}, {%0,%1,%2,%3};\n"
        : "+f"(c[0]), "+f"(c[1]), "+f"(c[2]), "+f"(c[3])
        : "r"(a[0]), "r"(a[1]), "r"(a[2]), "r"(a[3]), "r"(b[0]), "r"(b[1]));
}

__global__ __launch_bounds__(128) void gemm_tf32_kernel(GemmJobs jobs) {
    GemmJob jb = jobs.j[blockIdx.z];
    if ((int)blockIdx.y * BN >= jb.ncols) return;

    __shared__ float As[2][BM][BK + 4];
    __shared__ float Bs[2][BN][BK + 4];

    const int tid  = threadIdx.x;
    const int lane = tid & 31;
    const int warp = tid >> 5;
    const int g    = lane >> 2;   // groupID
    const int t4   = lane & 3;    // thread-in-group
    const int m0w  = (warp & 1) * 32;
    const int n0w  = (warp >> 1) * 32;

    const float* Ab = jb.A + (size_t)blockIdx.x * BM * Cdim;
    const float* Wb = jb.W + (size_t)blockIdx.y * BN * Cdim;

    const int lr = tid >> 3;         // 0..15
    const int lc = (tid & 7) * 4;    // 0,4,..,28

    float acc[2][4][4];
#pragma unroll
    for (int mt = 0; mt < 2; ++mt)
#pragma unroll
        for (int nt = 0; nt < 4; ++nt)
#pragma unroll
            for (int e = 0; e < 4; ++e) acc[mt][nt][e] = 0.f;

    float4 aReg[4], bReg[4];
    // prologue: tile 0
#pragma unroll
    for (int i = 0; i < 4; ++i) {
        aReg[i] = *(const float4*)(Ab + (size_t)(lr + i * 16) * Cdim + lc);
        bReg[i] = *(const float4*)(Wb + (size_t)(lr + i * 16) * Cdim + lc);
    }
#pragma unroll
    for (int i = 0; i < 4; ++i) {
        *(float4*)&As[0][lr + i * 16][lc] = aReg[i];
        *(float4*)&Bs[0][lr + i * 16][lc] = bReg[i];
    }
    __syncthreads();

    for (int kt = 0; kt < KTILES; ++kt) {
        const int buf = kt & 1;
        if (kt + 1 < KTILES) {
            const int ko = (kt + 1) * BK;
#pragma unroll
            for (int i = 0; i < 4; ++i) {
                aReg[i] = *(const float4*)(Ab + (size_t)(lr + i * 16) * Cdim + ko + lc);
                bReg[i] = *(const float4*)(Wb + (size_t)(lr + i * 16) * Cdim + ko + lc);
            }
        }
#pragma unroll
        for (int kk = 0; kk < BK / 8; ++kk) {
            const int k0 = kk * 8;
            unsigned afr[2][4];
#pragma unroll
            for (int mt = 0; mt < 2; ++mt) {
                const int mb = m0w + mt * 16;
                afr[mt][0] = f2tf(As[buf][mb + g][k0 + t4]);
                afr[mt][1] = f2tf(As[buf][mb + g + 8][k0 + t4]);
                afr[mt][2] = f2tf(As[buf][mb + g][k0 + t4 + 4]);
                afr[mt][3] = f2tf(As[buf][mb + g + 8][k0 + t4 + 4]);
            }
            unsigned bfr[4][2];
#pragma unroll
            for (int nt = 0; nt < 4; ++nt) {
                const int nb = n0w + nt * 8;
                bfr[nt][0] = f2tf(Bs[buf][nb + g][k0 + t4]);
                bfr[nt][1] = f2tf(Bs[buf][nb + g][k0 + t4 + 4]);
            }
#pragma unroll
            for (int mt = 0; mt < 2; ++mt)
#pragma unroll
                for (int nt = 0; nt < 4; ++nt)
                    mma8(acc[mt][nt], afr[mt], bfr[nt]);
        }
        if (kt + 1 < KTILES) {
            const int nb = buf ^ 1;
#pragma unroll
            for (int i = 0; i < 4; ++i) {
                *(float4*)&As[nb][lr + i * 16][lc] = aReg[i];
                *(float4*)&Bs[nb][lr + i * 16][lc] = bReg[i];
            }
            __syncthreads();
        }
    }

    // epilogue: bias (+ optional relu), fp32 store
    const int ldc = jb.ncols;
#pragma unroll
    for (int mt = 0; mt < 2; ++mt) {
#pragma unroll
        for (int nt = 0; nt < 4; ++nt) {
            const int row = (int)blockIdx.x * BM + m0w + mt * 16 + g;
            const int col = (int)blockIdx.y * BN + n0w + nt * 8 + t4 * 2;
            const float b0 = jb.bias[col];
            const float b1 = jb.bias[col + 1];
            float v0 = acc[mt][nt][0] + b0;
            float v1 = acc[mt][nt][1] + b1;
            float v2 = acc[mt][nt][2] + b0;
            float v3 = acc[mt][nt][3] + b1;
            if (jb.relu) {
                v0 = fmaxf(v0, 0.f); v1 = fmaxf(v1, 0.f);
                v2 = fmaxf(v2, 0.f); v3 = fmaxf(v3, 0.f);
            }
            *(float2*)(jb.C + (size_t)row * ldc + col)       = make_float2(v0, v1);
            *(float2*)(jb.C + (size_t)(row + 8) * ldc + col) = make_float2(v2, v3);
        }
    }
}

// ---------------- gating: alpha = softmax(h @ Wg2^T + bg2) -----------------
__device__ __forceinline__ float wsum(float p) {
#pragma unroll
    for (int off = 16; off; off >>= 1) p += __shfl_xor_sync(FULLMASK, p, off);
    return p;
}

__global__ __launch_bounds__(256) void gate_kernel(const float* __restrict__ Wg2,
                                                   const float* __restrict__ bg2) {
    const int w    = (int)((blockIdx.x * blockDim.x + threadIdx.x) >> 5);
    const int lane = threadIdx.x & 31;
    if (w >= Mrows) return;

    const float4 h = ((const float4*)(g_H + (size_t)w * Hdim))[lane];
    float d[3];
#pragma unroll
    for (int i = 0; i < 3; ++i) {
        const float4 ww = ((const float4*)(Wg2 + i * Hdim))[lane];
        float p = h.x * ww.x + h.y * ww.y + h.z * ww.z + h.w * ww.w;
        d[i] = wsum(p) + bg2[i];
    }
    const float m  = fmaxf(d[0], fmaxf(d[1], d[2]));
    const float e0 = __expf(d[0] - m);
    const float e1 = __expf(d[1] - m);
    const float e2 = __expf(d[2] - m);
    const float inv = 1.f / (e0 + e1 + e2);
    if (lane == 0) {
        g_alpha[(size_t)w * 3 + 0] = e0 * inv;
        g_alpha[(size_t)w * 3 + 1] = e1 * inv;
        g_alpha[(size_t)w * 3 + 2] = e2 * inv;
    }
}

// ------- fused: KNN attention x3 + LN x3 + alpha combine + final LN --------
__global__ __launch_bounds__(256) void attn_kernel(
    const float* __restrict__ x3, const int* __restrict__ knn,
    const float* __restrict__ ln_g, const float* __restrict__ ln_b,
    const float* __restrict__ fn_g, const float* __restrict__ fn_b,
    float* __restrict__ out) {
    const int w    = (int)((blockIdx.x * blockDim.x + threadIdx.x) >> 5);
    const int lane = threadIdx.x & 31;
    if (w >= Mrows) return;
    const int b = w / Npt;
    const int n = w - b * Npt;

    const float4* xr = (const float4*)(x3 + (size_t)w * Cdim);
    const float4 xa = xr[lane];
    const float4 xb = xr[lane + 32];

    const int idx_l = (lane < Kn) ? knn[n * Kn + lane] : 0;

    float alph[3];
#pragma unroll
    for (int i = 0; i < 3; ++i) alph[i] = g_alpha[(size_t)w * 3 + i];

    float acc[8] = {0.f, 0.f, 0.f, 0.f, 0.f, 0.f, 0.f, 0.f};

    for (int i = 0; i < 3; ++i) {
        const float4* qr = (const float4*)(g_Q + ((size_t)i * Mrows + w) * Cdim);
        const float4 qa = qr[lane];
        const float4 qb = qr[lane + 32];
        const float* Kbase = g_K + ((size_t)i * Mrows + (size_t)b * Npt) * Cdim;
        const float* Vbase = g_V + ((size_t)i * Mrows + (size_t)b * Npt) * Cdim;

        float s[Kn];
#pragma unroll
        for (int k = 0; k < Kn; ++k) {
            const int j = __shfl_sync(FULLMASK, idx_l, k);
            const float4* kr = (const float4*)(Kbase + (size_t)j * Cdim);
            const float4 ka = kr[lane];
            const float4 kb = kr[lane + 32];
            float p = qa.x * ka.x + qa.y * ka.y + qa.z * ka.z + qa.w * ka.w
                    + qb.x * kb.x + qb.y * kb.y + qb.z * kb.z + qb.w * kb.w;
            s[k] = wsum(p) * 0.0625f;   // 1/sqrt(256)
        }
        float m = s[0];
#pragma unroll
        for (int k = 1; k < Kn; ++k) m = fmaxf(m, s[k]);
        float ssum = 0.f;
#pragma unroll
        for (int k = 0; k < Kn; ++k) { s[k] = __expf(s[k] - m); ssum += s[k]; }
        const float sinv = 1.f / ssum;

        float o[8] = {0.f, 0.f, 0.f, 0.f, 0.f, 0.f, 0.f, 0.f};
#pragma unroll
        for (int k = 0; k < Kn; ++k) {
            const int j = __shfl_sync(FULLMASK, idx_l, k);
            const float4* vr = (const float4*)(Vbase + (size_t)j * Cdim);
            const float4 va = vr[lane];
            const float4 vb = vr[lane + 32];
            const float aw = s[k] * sinv;
            o[0] += aw * va.x; o[1] += aw * va.y; o[2] += aw * va.z; o[3] += aw * va.w;
            o[4] += aw * vb.x; o[5] += aw * vb.y; o[6] += aw * vb.z; o[7] += aw * vb.w;
        }
        float r[8];
        r[0] = o[0] + qa.x; r[1] = o[1] + qa.y; r[2] = o[2] + qa.z; r[3] = o[3] + qa.w;
        r[4] = o[4] + qb.x; r[5] = o[5] + qb.y; r[6] = o[6] + qb.z; r[7] = o[7] + qb.w;

        float part = 0.f;
#pragma unroll
        for (int t = 0; t < 8; ++t) part += r[t];
        const float mean = wsum(part) * (1.f / Cdim);
        float vpart = 0.f;
#pragma unroll
        for (int t = 0; t < 8; ++t) { const float d = r[t] - mean; vpart += d * d; }
        const float var  = wsum(vpart) * (1.f / Cdim);
        const float rstd = rsqrtf(var + 1e-5f);

        const float4 ga = ((const float4*)(ln_g + i * Cdim))[lane];
        const float4 gb = ((const float4*)(ln_g + i * Cdim))[lane + 32];
        const float4 ba = ((const float4*)(ln_b + i * Cdim))[lane];
        const float4 bb = ((const float4*)(ln_b + i * Cdim))[lane + 32];
        const float al = alph[i];
        acc[0] += al * ((r[0] - mean) * rstd * ga.x + ba.x);
        acc[1] += al * ((r[1] - mean) * rstd * ga.y + ba.y);
        acc[2] += al * ((r[2] - mean) * rstd * ga.z + ba.z);
        acc[3] += al * ((r[3] - mean) * rstd * ga.w + ba.w);
        acc[4] += al * ((r[4] - mean) * rstd * gb.x + bb.x);
        acc[5] += al * ((r[5] - mean) * rstd * gb.y + bb.y);
        acc[6] += al * ((r[6] - mean) * rstd * gb.z + bb.z);
        acc[7] += al * ((r[7] - mean) * rstd * gb.w + bb.w);
    }

    // final residual + LN
    float r[8];
    r[0] = acc[0] + xa.x; r[1] = acc[1] + xa.y; r[2] = acc[2] + xa.z; r[3] = acc[3] + xa.w;
    r[4] = acc[4] + xb.x; r[5] = acc[5] + xb.y; r[6] = acc[6] + xb.z; r[7] = acc[7] + xb.w;
    float part = 0.f;
#pragma unroll
    for (int t = 0; t < 8; ++t) part += r[t];
    const float mean = wsum(part) * (1.f / Cdim);
    float vpart = 0.f;
#pragma unroll
    for (int t = 0; t < 8; ++t) { const float d = r[t] - mean; vpart += d * d; }
    const float var  = wsum(vpart) * (1.f / Cdim);
    const float rstd = rsqrtf(var + 1e-5f);

    const float4 ga = ((const float4*)fn_g)[lane];
    const float4 gb = ((const float4*)fn_g)[lane + 32];
    const float4 ba = ((const float4*)fn_b)[lane];
    const float4 bb = ((const float4*)fn_b)[lane + 32];

    float4 oa, ob;
    oa.x = (r[0] - mean) * rstd * ga.x + ba.x;
    oa.y = (r[1] - mean) * rstd * ga.y + ba.y;
    oa.z = (r[2] - mean) * rstd * ga.z + ba.z;
    oa.w = (r[3] - mean) * rstd * ga.w + ba.w;
    ob.x = (r[4] - mean) * rstd * gb.x + bb.x;
    ob.y = (r[5] - mean) * rstd * gb.y + bb.y;
    ob.z = (r[6] - mean) * rstd * gb.z + bb.z;
    ob.w = (r[7] - mean) * rstd * gb.w + bb.w;

    float4* orow = (float4*)(out + (size_t)w * Cdim);
    orow[lane]      = oa;
    orow[lane + 32] = ob;
}

// --------------------------------- launch ----------------------------------
extern "C" void kernel_launch(void* const* d_in, const int* in_sizes, int n_in,
                              void* d_out, int out_size) {
    const float* x0   = (const float*)d_in[0];
    const float* x1   = (const float*)d_in[1];
    const float* x2   = (const float*)d_in[2];
    const float* x3   = (const float*)d_in[3];
    const int*   knn  = (const int*)d_in[4];
    const float* Wq   = (const float*)d_in[5];
    const float* bq   = (const float*)d_in[6];
    const float* Wk   = (const float*)d_in[7];
    const float* bk   = (const float*)d_in[8];
    const float* Wv   = (const float*)d_in[9];
    const float* bv   = (const float*)d_in[10];
    const float* ln_g = (const float*)d_in[11];
    const float* ln_b = (const float*)d_in[12];
    const float* Wg1  = (const float*)d_in[13];
    const float* bg1  = (const float*)d_in[14];
    const float* Wg2  = (const float*)d_in[15];
    const float* bg2  = (const float*)d_in[16];
    const float* fn_g = (const float*)d_in[17];
    const float* fn_b = (const float*)d_in[18];
    float* out = (float*)d_out;

    float *Qp, *Kp, *Vp, *Hp;
    cudaGetSymbolAddress((void**)&Qp, g_Q);
    cudaGetSymbolAddress((void**)&Kp, g_K);
    cudaGetSymbolAddress((void**)&Vp, g_V);
    cudaGetSymbolAddress((void**)&Hp, g_H);

    GemmJobs jobs;
    const float* xs[3] = {x0, x1, x2};
    const size_t S = (size_t)Mrows * Cdim;
    for (int i = 0; i < 3; ++i) {
        jobs.j[i]     = { xs[i], Wq + (size_t)i * Cdim * Cdim, bq + i * Cdim, Qp + (size_t)i * S, Cdim, 0 };
        jobs.j[3 + i] = { x3,    Wk + (size_t)i * Cdim * Cdim, bk + i * Cdim, Kp + (size_t)i * S, Cdim, 0 };
        jobs.j[6 + i] = { x3,    Wv + (size_t)i * Cdim * Cdim, bv + i * Cdim, Vp + (size_t)i * S, Cdim, 0 };
    }
    jobs.j[9] = { x3, Wg1, bg1, Hp, Hdim, 1 };

    dim3 gg(Mrows / BM, Cdim / BN, 10);   // 625 x 4 x 10
    gemm_tf32_kernel<<<gg, 128>>>(jobs);

    const int warpsBlocks = (Mrows * 32 + 255) / 256;   // 5000
    gate_kernel<<<warpsBlocks, 256>>>(Wg2, bg2);
    attn_kernel<<<warpsBlocks, 256>>>(x3, knn, ln_g, ln_b, fn_g, fn_b, out);
}

// round 2
// speedup vs baseline: 1.4732x; 1.4732x over previous
#include <cuda_runtime.h>
#include <cstdint>
#include <cstddef>

#define FULLMASK 0xffffffffu

constexpr int Bx    = 2;
constexpr int Npt   = 20000;
constexpr int Cdim  = 256;
constexpr int Kn    = 16;
constexpr int Hdim  = 128;
constexpr int Mrows = Bx * Npt;   // 40000

// ---------------- scratch (device globals: allocation-free) ----------------
__device__ float g_Q[(size_t)3 * Mrows * Cdim];
__device__ float g_K[(size_t)3 * Mrows * Cdim];
__device__ float g_V[(size_t)3 * Mrows * Cdim];
__device__ float g_H[(size_t)Mrows * Hdim];
__device__ float g_alpha[(size_t)Mrows * 3];

// ---------------- tf32 GEMM:  C[M,N] = A[M,256] @ W[N,256]^T + bias --------
struct GemmJob {
    const float* A;
    const float* W;
    const float* bias;
    float*       C;
    int          ncols;
    int          relu;
};
struct GemmJobs { GemmJob j[10]; };

constexpr int BM = 64, BN = 64, BK = 32;
constexpr int KTILES = Cdim / BK;   // 8

__device__ __forceinline__ unsigned f2tf(float x) {
    unsigned r;
    asm("cvt.rna.tf32.f32 %0, %1;" : "=r"(r) : "f"(x));
    return r;
}

__device__ __forceinline__ void mma8(float c[4], const unsigned a[4], const unsigned b[2]) {
    asm volatile(
        "mma.sync.aligned.m16n8k8.row.col.f32.tf32.tf32.f32 "
        "{%0,%1,%2,%3}, {%4,%5,%6,%7}, {%8,%9}, {%0,%1,%2,%3};\n"
        : "+f"(c[0]), "+f"(c[1]), "+f"(c[2]), "+f"(c[3])
        : "r"(a[0]), "r"(a[1]), "r"(a[2]), "r"(a[3]), "r"(b[0]), "r"(b[1]));
}

// convert a staged float4 to tf32 bits packed in uint4
__device__ __forceinline__ uint4 cvt4(float4 v) {
    uint4 r;
    r.x = f2tf(v.x); r.y = f2tf(v.y); r.z = f2tf(v.z); r.w = f2tf(v.w);
    return r;
}

__global__ __launch_bounds__(128) void gemm_tf32_kernel(GemmJobs jobs) {
    GemmJob jb = jobs.j[blockIdx.z];
    if ((int)blockIdx.y * BN >= jb.ncols) return;

    // smem holds tf32 bit patterns (converted once at store time)
    __shared__ unsigned As[2][BM][BK + 4];
    __shared__ unsigned Bs[2][BN][BK + 4];

    const int tid  = threadIdx.x;
    const int lane = tid & 31;
    const int warp = tid >> 5;
    const int g    = lane >> 2;   // groupID
    const int t4   = lane & 3;    // thread-in-group
    const int m0w  = (warp & 1) * 32;
    const int n0w  = (warp >> 1) * 32;

    const float* Ab = jb.A + (size_t)blockIdx.x * BM * Cdim;
    const float* Wb = jb.W + (size_t)blockIdx.y * BN * Cdim;

    const int lr = tid >> 3;         // 0..15
    const int lc = (tid & 7) * 4;    // 0,4,..,28

    float acc[2][4][4];
#pragma unroll
    for (int mt = 0; mt < 2; ++mt)
#pragma unroll
        for (int nt = 0; nt < 4; ++nt)
#pragma unroll
            for (int e = 0; e < 4; ++e) acc[mt][nt][e] = 0.f;

    float4 aReg[4], bReg[4];
    // prologue: tile 0
#pragma unroll
    for (int i = 0; i < 4; ++i) {
        aReg[i] = *(const float4*)(Ab + (size_t)(lr + i * 16) * Cdim + lc);
        bReg[i] = *(const float4*)(Wb + (size_t)(lr + i * 16) * Cdim + lc);
    }
#pragma unroll
    for (int i = 0; i < 4; ++i) {
        *(uint4*)&As[0][lr + i * 16][lc] = cvt4(aReg[i]);
        *(uint4*)&Bs[0][lr + i * 16][lc] = cvt4(bReg[i]);
    }
    __syncthreads();

    for (int kt = 0; kt < KTILES; ++kt) {
        const int buf = kt & 1;
        if (kt + 1 < KTILES) {
            const int ko = (kt + 1) * BK;
#pragma unroll
            for (int i = 0; i < 4; ++i) {
                aReg[i] = *(const float4*)(Ab + (size_t)(lr + i * 16) * Cdim + ko + lc);
                bReg[i] = *(const float4*)(Wb + (size_t)(lr + i * 16) * Cdim + ko + lc);
            }
        }
#pragma unroll
        for (int kk = 0; kk < BK / 8; ++kk) {
            const int k0 = kk * 8;
            unsigned afr[2][4];
#pragma unroll
            for (int mt = 0; mt < 2; ++mt) {
                const int mb = m0w + mt * 16;
                afr[mt][0] = As[buf][mb + g][k0 + t4];
                afr[mt][1] = As[buf][mb + g + 8][k0 + t4];
                afr[mt][2] = As[buf][mb + g][k0 + t4 + 4];
                afr[mt][3] = As[buf][mb + g + 8][k0 + t4 + 4];
            }
            unsigned bfr[4][2];
#pragma unroll
            for (int nt = 0; nt < 4; ++nt) {
                const int nb = n0w + nt * 8;
                bfr[nt][0] = Bs[buf][nb + g][k0 + t4];
                bfr[nt][1] = Bs[buf][nb + g][k0 + t4 + 4];
            }
#pragma unroll
            for (int mt = 0; mt < 2; ++mt)
#pragma unroll
                for (int nt = 0; nt < 4; ++nt)
                    mma8(acc[mt][nt], afr[mt], bfr[nt]);
        }
        if (kt + 1 < KTILES) {
            const int nb = buf ^ 1;
#pragma unroll
            for (int i = 0; i < 4; ++i) {
                *(uint4*)&As[nb][lr + i * 16][lc] = cvt4(aReg[i]);
                *(uint4*)&Bs[nb][lr + i * 16][lc] = cvt4(bReg[i]);
            }
            __syncthreads();
        }
    }

    // epilogue: bias (+ optional relu), fp32 store
    const int ldc = jb.ncols;
#pragma unroll
    for (int mt = 0; mt < 2; ++mt) {
#pragma unroll
        for (int nt = 0; nt < 4; ++nt) {
            const int row = (int)blockIdx.x * BM + m0w + mt * 16 + g;
            const int col = (int)blockIdx.y * BN + n0w + nt * 8 + t4 * 2;
            const float b0 = jb.bias[col];
            const float b1 = jb.bias[col + 1];
            float v0 = acc[mt][nt][0] + b0;
            float v1 = acc[mt][nt][1] + b1;
            float v2 = acc[mt][nt][2] + b0;
            float v3 = acc[mt][nt][3] + b1;
            if (jb.relu) {
                v0 = fmaxf(v0, 0.f); v1 = fmaxf(v1, 0.f);
                v2 = fmaxf(v2, 0.f); v3 = fmaxf(v3, 0.f);
            }
            *(float2*)(jb.C + (size_t)row * ldc + col)       = make_float2(v0, v1);
            *(float2*)(jb.C + (size_t)(row + 8) * ldc + col) = make_float2(v2, v3);
        }
    }
}

// ---------------- gating: alpha = softmax(h @ Wg2^T + bg2) -----------------
__device__ __forceinline__ float wsum(float p) {
#pragma unroll
    for (int off = 16; off; off >>= 1) p += __shfl_xor_sync(FULLMASK, p, off);
    return p;
}

__global__ __launch_bounds__(256) void gate_kernel(const float* __restrict__ Wg2,
                                                   const float* __restrict__ bg2) {
    const int w    = (int)((blockIdx.x * blockDim.x + threadIdx.x) >> 5);
    const int lane = threadIdx.x & 31;
    if (w >= Mrows) return;

    const float4 h = ((const float4*)(g_H + (size_t)w * Hdim))[lane];
    float d[3];
#pragma unroll
    for (int i = 0; i < 3; ++i) {
        const float4 ww = ((const float4*)(Wg2 + i * Hdim))[lane];
        float p = h.x * ww.x + h.y * ww.y + h.z * ww.z + h.w * ww.w;
        d[i] = wsum(p) + bg2[i];
    }
    const float m  = fmaxf(d[0], fmaxf(d[1], d[2]));
    const float e0 = __expf(d[0] - m);
    const float e1 = __expf(d[1] - m);
    const float e2 = __expf(d[2] - m);
    const float inv = 1.f / (e0 + e1 + e2);
    if (lane == 0) {
        g_alpha[(size_t)w * 3 + 0] = e0 * inv;
        g_alpha[(size_t)w * 3 + 1] = e1 * inv;
        g_alpha[(size_t)w * 3 + 2] = e2 * inv;
    }
}

// ------- fused: KNN attention x3 + LN x3 + alpha combine + final LN --------
__global__ __launch_bounds__(256) void attn_kernel(
    const float* __restrict__ x3, const int* __restrict__ knn,
    const float* __restrict__ ln_g, const float* __restrict__ ln_b,
    const float* __restrict__ fn_g, const float* __restrict__ fn_b,
    float* __restrict__ out) {
    const int w    = (int)((blockIdx.x * blockDim.x + threadIdx.x) >> 5);
    const int lane = threadIdx.x & 31;
    if (w >= Mrows) return;
    const int b = w / Npt;
    const int n = w - b * Npt;

    const float4* xr = (const float4*)(x3 + (size_t)w * Cdim);
    const float4 xa = xr[lane];
    const float4 xb = xr[lane + 32];

    const int idx_l = (lane < Kn) ? knn[n * Kn + lane] : 0;

    float alph[3];
#pragma unroll
    for (int i = 0; i < 3; ++i) alph[i] = g_alpha[(size_t)w * 3 + i];

    float acc[8] = {0.f, 0.f, 0.f, 0.f, 0.f, 0.f, 0.f, 0.f};

    for (int i = 0; i < 3; ++i) {
        const float4* qr = (const float4*)(g_Q + ((size_t)i * Mrows + w) * Cdim);
        const float4 qa = qr[lane];
        const float4 qb = qr[lane + 32];
        const float* Kbase = g_K + ((size_t)i * Mrows + (size_t)b * Npt) * Cdim;
        const float* Vbase = g_V + ((size_t)i * Mrows + (size_t)b * Npt) * Cdim;

        float s[Kn];
#pragma unroll
        for (int k = 0; k < Kn; ++k) {
            const int j = __shfl_sync(FULLMASK, idx_l, k);
            const float4* kr = (const float4*)(Kbase + (size_t)j * Cdim);
            const float4 ka = kr[lane];
            const float4 kb = kr[lane + 32];
            float p = qa.x * ka.x + qa.y * ka.y + qa.z * ka.z + qa.w * ka.w
                    + qb.x * kb.x + qb.y * kb.y + qb.z * kb.z + qb.w * kb.w;
            s[k] = wsum(p) * 0.0625f;   // 1/sqrt(256)
        }
        float m = s[0];
#pragma unroll
        for (int k = 1; k < Kn; ++k) m = fmaxf(m, s[k]);
        float ssum = 0.f;
#pragma unroll
        for (int k = 0; k < Kn; ++k) { s[k] = __expf(s[k] - m); ssum += s[k]; }
        const float sinv = 1.f / ssum;

        float o[8] = {0.f, 0.f, 0.f, 0.f, 0.f, 0.f, 0.f, 0.f};
#pragma unroll
        for (int k = 0; k < Kn; ++k) {
            const int j = __shfl_sync(FULLMASK, idx_l, k);
            const float4* vr = (const float4*)(Vbase + (size_t)j * Cdim);
            const float4 va = vr[lane];
            const float4 vb = vr[lane + 32];
            const float aw = s[k] * sinv;
            o[0] += aw * va.x; o[1] += aw * va.y; o[2] += aw * va.z; o[3] += aw * va.w;
            o[4] += aw * vb.x; o[5] += aw * vb.y; o[6] += aw * vb.z; o[7] += aw * vb.w;
        }
        float r[8];
        r[0] = o[0] + qa.x; r[1] = o[1] + qa.y; r[2] = o[2] + qa.z; r[3] = o[3] + qa.w;
        r[4] = o[4] + qb.x; r[5] = o[5] + qb.y; r[6] = o[6] + qb.z; r[7] = o[7] + qb.w;

        float part = 0.f;
#pragma unroll
        for (int t = 0; t < 8; ++t) part += r[t];
        const float mean = wsum(part) * (1.f / Cdim);
        float vpart = 0.f;
#pragma unroll
        for (int t = 0; t < 8; ++t) { const float d = r[t] - mean; vpart += d * d; }
        const float var  = wsum(vpart) * (1.f / Cdim);
        const float rstd = rsqrtf(var + 1e-5f);

        const float4 ga = ((const float4*)(ln_g + i * Cdim))[lane];
        const float4 gb = ((const float4*)(ln_g + i * Cdim))[lane + 32];
        const float4 ba = ((const float4*)(ln_b + i * Cdim))[lane];
        const float4 bb = ((const float4*)(ln_b + i * Cdim))[lane + 32];
        const float al = alph[i];
        acc[0] += al * ((r[0] - mean) * rstd * ga.x + ba.x);
        acc[1] += al * ((r[1] - mean) * rstd * ga.y + ba.y);
        acc[2] += al * ((r[2] - mean) * rstd * ga.z + ba.z);
        acc[3] += al * ((r[3] - mean) * rstd * ga.w + ba.w);
        acc[4] += al * ((r[4] - mean) * rstd * gb.x + bb.x);
        acc[5] += al * ((r[5] - mean) * rstd * gb.y + bb.y);
        acc[6] += al * ((r[6] - mean) * rstd * gb.z + bb.z);
        acc[7] += al * ((r[7] - mean) * rstd * gb.w + bb.w);
    }

    // final residual + LN
    float r[8];
    r[0] = acc[0] + xa.x; r[1] = acc[1] + xa.y; r[2] = acc[2] + xa.z; r[3] = acc[3] + xa.w;
    r[4] = acc[4] + xb.x; r[5] = acc[5] + xb.y; r[6] = acc[6] + xb.z; r[7] = acc[7] + xb.w;
    float part = 0.f;
#pragma unroll
    for (int t = 0; t < 8; ++t) part += r[t];
    const float mean = wsum(part) * (1.f / Cdim);
    float vpart = 0.f;
#pragma unroll
    for (int t = 0; t < 8; ++t) { const float d = r[t] - mean; vpart += d * d; }
    const float var  = wsum(vpart) * (1.f / Cdim);
    const float rstd = rsqrtf(var + 1e-5f);

    const float4 ga = ((const float4*)fn_g)[lane];
    const float4 gb = ((const float4*)fn_g)[lane + 32];
    const float4 ba = ((const float4*)fn_b)[lane];
    const float4 bb = ((const float4*)fn_b)[lane + 32];

    float4 oa, ob;
    oa.x = (r[0] - mean) * rstd * ga.x + ba.x;
    oa.y = (r[1] - mean) * rstd * ga.y + ba.y;
    oa.z = (r[2] - mean) * rstd * ga.z + ba.z;
    oa.w = (r[3] - mean) * rstd * ga.w + ba.w;
    ob.x = (r[4] - mean) * rstd * gb.x + bb.x;
    ob.y = (r[5] - mean) * rstd * gb.y + bb.y;
    ob.z = (r[6] - mean) * rstd * gb.z + bb.z;
    ob.w = (r[7] - mean) * rstd * gb.w + bb.w;

    float4* orow = (float4*)(out + (size_t)w * Cdim);
    orow[lane]      = oa;
    orow[lane + 32] = ob;
}

// --------------------------------- launch ----------------------------------
extern "C" void kernel_launch(void* const* d_in, const int* in_sizes, int n_in,
                              void* d_out, int out_size) {
    const float* x0   = (const float*)d_in[0];
    const float* x1   = (const float*)d_in[1];
    const float* x2   = (const float*)d_in[2];
    const float* x3   = (const float*)d_in[3];
    const int*   knn  = (const int*)d_in[4];
    const float* Wq   = (const float*)d_in[5];
    const float* bq   = (const float*)d_in[6];
    const float* Wk   = (const float*)d_in[7];
    const float* bk   = (const float*)d_in[8];
    const float* Wv   = (const float*)d_in[9];
    const float* bv   = (const float*)d_in[10];
    const float* ln_g = (const float*)d_in[11];
    const float* ln_b = (const float*)d_in[12];
    const float* Wg1  = (const float*)d_in[13];
    const float* bg1  = (const float*)d_in[14];
    const float* Wg2  = (const float*)d_in[15];
    const float* bg2  = (const float*)d_in[16];
    const float* fn_g = (const float*)d_in[17];
    const float* fn_b = (const float*)d_in[18];
    float* out = (float*)d_out;

    float *Qp, *Kp, *Vp, *Hp;
    cudaGetSymbolAddress((void**)&Qp, g_Q);
    cudaGetSymbolAddress((void**)&Kp, g_K);
    cudaGetSymbolAddress((void**)&Vp, g_V);
    cudaGetSymbolAddress((void**)&Hp, g_H);

    GemmJobs jobs;
    const float* xs[3] = {x0, x1, x2};
    const size_t S = (size_t)Mrows * Cdim;
    for (int i = 0; i < 3; ++i) {
        jobs.j[i]     = { xs[i], Wq + (size_t)i * Cdim * Cdim, bq + i * Cdim, Qp + (size_t)i * S, Cdim, 0 };
        jobs.j[3 + i] = { x3,    Wk + (size_t)i * Cdim * Cdim, bk + i * Cdim, Kp + (size_t)i * S, Cdim, 0 };
        jobs.j[6 + i] = { x3,    Wv + (size_t)i * Cdim * Cdim, bv + i * Cdim, Vp + (size_t)i * S, Cdim, 0 };
    }
    jobs.j[9] = { x3, Wg1, bg1, Hp, Hdim, 1 };

    dim3 gg(Mrows / BM, Cdim / BN, 10);   // 625 x 4 x 10
    gemm_tf32_kernel<<<gg, 128>>>(jobs);

    const int warpsBlocks = (Mrows * 32 + 255) / 256;   // 5000
    gate_kernel<<<warpsBlocks, 256>>>(Wg2, bg2);
    attn_kernel<<<warpsBlocks, 256>>>(x3, knn, ln_g, ln_b, fn_g, fn_b, out);
}

// round 3
// speedup vs baseline: 2.1371x; 1.4506x over previous
#include <cuda_runtime.h>
#include <cuda_fp16.h>
#include <cstdint>
#include <cstddef>

#define FULLMASK 0xffffffffu

constexpr int Bx    = 2;
constexpr int Npt   = 20000;
constexpr int Cdim  = 256;
constexpr int Kn    = 16;
constexpr int Hdim  = 128;
constexpr int Mrows = Bx * Npt;   // 40000

// ---------------- scratch (device globals: allocation-free) ----------------
__device__ float  g_Q[(size_t)3 * Mrows * Cdim];
__device__ __half g_K[(size_t)3 * Mrows * Cdim];
__device__ __half g_V[(size_t)3 * Mrows * Cdim];
__device__ float  g_H[(size_t)Mrows * Hdim];
__device__ float  g_alpha[(size_t)Mrows * 3];

// ---------------- tf32 GEMM:  C[M,N] = A[M,256] @ W[N,256]^T + bias --------
struct GemmJob {
    const float* A;
    const float* W;
    const float* bias;
    void*        C;
    int          ncols;
    int          relu;
    int          half_out;
};
struct GemmJobs { GemmJob j[10]; };

constexpr int BM = 128, BN = 128, BK = 32;
constexpr int LDSM = BK + 4;                 // 36: (4g+t4)%32 unique -> conflict-free
constexpr int KTILES = Cdim / BK;            // 8
constexpr int SMEM_BYTES = 2 * (BM + BN) * LDSM * 4;  // 73728

__device__ __forceinline__ unsigned f2tf(float x) {
    unsigned r;
    asm("cvt.rna.tf32.f32 %0, %1;" : "=r"(r) : "f"(x));
    return r;
}
__device__ __forceinline__ uint4 cvt4(float4 v) {
    uint4 r;
    r.x = f2tf(v.x); r.y = f2tf(v.y); r.z = f2tf(v.z); r.w = f2tf(v.w);
    return r;
}
__device__ __forceinline__ void mma8(float c[4], const unsigned a[4], const unsigned b[2]) {
    asm volatile(
        "mma.sync.aligned.m16n8k8.row.col.f32.tf32.tf32.f32 "
        "{%0,%1,%2,%3}, {%4,%5,%6,%7}, {%8,%9}, {%0,%1,%2,%3};\n"
        : "+f"(c[0]), "+f"(c[1]), "+f"(c[2]), "+f"(c[3])
        : "r"(a[0]), "r"(a[1]), "r"(a[2]), "r"(a[3]), "r"(b[0]), "r"(b[1]));
}

__global__ __launch_bounds__(256) void gemm_tf32_kernel(GemmJobs jobs) {
    GemmJob jb = jobs.j[blockIdx.z];
    if ((int)blockIdx.y * BN >= jb.ncols) return;

    extern __shared__ unsigned smemRaw[];
    unsigned* sA = smemRaw;                       // [2][BM][LDSM]
    unsigned* sB = smemRaw + 2 * BM * LDSM;       // [2][BN][LDSM]
#define AS(b, r, c) sA[((b) * BM + (r)) * LDSM + (c)]
#define BS(b, r, c) sB[((b) * BN + (r)) * LDSM + (c)]

    const int tid  = threadIdx.x;
    const int lane = tid & 31;
    const int warp = tid >> 5;       // 0..7
    const int g    = lane >> 2;      // groupID 0..7
    const int t4   = lane & 3;       // 0..3
    const int m0w  = (warp & 1) * 64;
    const int n0w  = (warp >> 1) * 32;

    const int lr = tid >> 3;         // 0..31
    const int lc = (tid & 7) * 4;    // 0,4,..,28

    const int rowBase = (int)blockIdx.x * BM;
    const float* Wb = jb.W + (size_t)blockIdx.y * BN * Cdim;

    float acc[4][4][4];
#pragma unroll
    for (int mt = 0; mt < 4; ++mt)
#pragma unroll
        for (int nt = 0; nt < 4; ++nt)
#pragma unroll
            for (int e = 0; e < 4; ++e) acc[mt][nt][e] = 0.f;

    float4 aReg[4], bReg[4];
    // prologue: ktile 0
#pragma unroll
    for (int i = 0; i < 4; ++i) {
        const int ra = min(rowBase + lr + i * 32, Mrows - 1);
        aReg[i] = *(const float4*)(jb.A + (size_t)ra * Cdim + lc);
        bReg[i] = *(const float4*)(Wb + (size_t)(lr + i * 32) * Cdim + lc);
    }
#pragma unroll
    for (int i = 0; i < 4; ++i) {
        *(uint4*)&AS(0, lr + i * 32, lc) = cvt4(aReg[i]);
        *(uint4*)&BS(0, lr + i * 32, lc) = cvt4(bReg[i]);
    }
    __syncthreads();

    for (int kt = 0; kt < KTILES; ++kt) {
        const int buf = kt & 1;
        if (kt + 1 < KTILES) {
            const int ko = (kt + 1) * BK;
#pragma unroll
            for (int i = 0; i < 4; ++i) {
                const int ra = min(rowBase + lr + i * 32, Mrows - 1);
                aReg[i] = *(const float4*)(jb.A + (size_t)ra * Cdim + ko + lc);
                bReg[i] = *(const float4*)(Wb + (size_t)(lr + i * 32) * Cdim + ko + lc);
            }
        }
#pragma unroll
        for (int kk = 0; kk < BK / 8; ++kk) {
            const int k0 = kk * 8;
            unsigned afr[4][4];
#pragma unroll
            for (int mt = 0; mt < 4; ++mt) {
                const int mb = m0w + mt * 16;
                afr[mt][0] = AS(buf, mb + g,     k0 + t4);
                afr[mt][1] = AS(buf, mb + g + 8, k0 + t4);
                afr[mt][2] = AS(buf, mb + g,     k0 + t4 + 4);
                afr[mt][3] = AS(buf, mb + g + 8, k0 + t4 + 4);
            }
            unsigned bfr[4][2];
#pragma unroll
            for (int nt = 0; nt < 4; ++nt) {
                const int nb = n0w + nt * 8;
                bfr[nt][0] = BS(buf, nb + g, k0 + t4);
                bfr[nt][1] = BS(buf, nb + g, k0 + t4 + 4);
            }
#pragma unroll
            for (int mt = 0; mt < 4; ++mt)
#pragma unroll
                for (int nt = 0; nt < 4; ++nt)
                    mma8(acc[mt][nt], afr[mt], bfr[nt]);
        }
        if (kt + 1 < KTILES) {
            const int nb = buf ^ 1;
#pragma unroll
            for (int i = 0; i < 4; ++i) {
                *(uint4*)&AS(nb, lr + i * 32, lc) = cvt4(aReg[i]);
                *(uint4*)&BS(nb, lr + i * 32, lc) = cvt4(bReg[i]);
            }
            __syncthreads();
        }
    }

    // epilogue: bias (+relu), fp32 or fp16 store, row-guarded
    const int ldc = jb.ncols;
#pragma unroll
    for (int mt = 0; mt < 4; ++mt) {
#pragma unroll
        for (int nt = 0; nt < 4; ++nt) {
            const int row = rowBase + m0w + mt * 16 + g;
            const int col = (int)blockIdx.y * BN + n0w + nt * 8 + t4 * 2;
            const float b0 = jb.bias[col];
            const float b1 = jb.bias[col + 1];
            float v0 = acc[mt][nt][0] + b0;
            float v1 = acc[mt][nt][1] + b1;
            float v2 = acc[mt][nt][2] + b0;
            float v3 = acc[mt][nt][3] + b1;
            if (jb.relu) {
                v0 = fmaxf(v0, 0.f); v1 = fmaxf(v1, 0.f);
                v2 = fmaxf(v2, 0.f); v3 = fmaxf(v3, 0.f);
            }
            if (jb.half_out) {
                __half* C = (__half*)jb.C;
                if (row < Mrows)
                    *(__half2*)(C + (size_t)row * ldc + col) = __floats2half2_rn(v0, v1);
                if (row + 8 < Mrows)
                    *(__half2*)(C + (size_t)(row + 8) * ldc + col) = __floats2half2_rn(v2, v3);
            } else {
                float* C = (float*)jb.C;
                if (row < Mrows)
                    *(float2*)(C + (size_t)row * ldc + col) = make_float2(v0, v1);
                if (row + 8 < Mrows)
                    *(float2*)(C + (size_t)(row + 8) * ldc + col) = make_float2(v2, v3);
            }
        }
    }
#undef AS
#undef BS
}

// ---------------- gating: alpha = softmax(h @ Wg2^T + bg2) -----------------
__device__ __forceinline__ float wsum(float p) {
#pragma unroll
    for (int off = 16; off; off >>= 1) p += __shfl_xor_sync(FULLMASK, p, off);
    return p;
}

__global__ __launch_bounds__(256) void gate_kernel(const float* __restrict__ Wg2,
                                                   const float* __restrict__ bg2) {
    const int w    = (int)((blockIdx.x * blockDim.x + threadIdx.x) >> 5);
    const int lane = threadIdx.x & 31;
    if (w >= Mrows) return;

    const float4 h = ((const float4*)(g_H + (size_t)w * Hdim))[lane];
    float d[3];
#pragma unroll
    for (int i = 0; i < 3; ++i) {
        const float4 ww = ((const float4*)(Wg2 + i * Hdim))[lane];
        float p = h.x * ww.x + h.y * ww.y + h.z * ww.z + h.w * ww.w;
        d[i] = wsum(p) + bg2[i];
    }
    const float m  = fmaxf(d[0], fmaxf(d[1], d[2]));
    const float e0 = __expf(d[0] - m);
    const float e1 = __expf(d[1] - m);
    const float e2 = __expf(d[2] - m);
    const float inv = 1.f / (e0 + e1 + e2);
    if (lane == 0) {
        g_alpha[(size_t)w * 3 + 0] = e0 * inv;
        g_alpha[(size_t)w * 3 + 1] = e1 * inv;
        g_alpha[(size_t)w * 3 + 2] = e2 * inv;
    }
}

// ------- fused: KNN attention x3 + LN x3 + alpha combine + final LN --------
// lane owns channels [8*lane, 8*lane+8): one uint4 (8 halfs) per K/V row.
__device__ __forceinline__ float dot8h(float4 qa, float4 qb, uint4 kv) {
    const __half2* kh = (const __half2*)&kv;
    const float2 f0 = __half22float2(kh[0]);
    const float2 f1 = __half22float2(kh[1]);
    const float2 f2 = __half22float2(kh[2]);
    const float2 f3 = __half22float2(kh[3]);
    return qa.x * f0.x + qa.y * f0.y + qa.z * f1.x + qa.w * f1.y
         + qb.x * f2.x + qb.y * f2.y + qb.z * f3.x + qb.w * f3.y;
}

__global__ __launch_bounds__(256) void attn_kernel(
    const float* __restrict__ x3, const int* __restrict__ knn,
    const float* __restrict__ ln_g, const float* __restrict__ ln_b,
    const float* __restrict__ fn_g, const float* __restrict__ fn_b,
    float* __restrict__ out) {
    const int w    = (int)((blockIdx.x * blockDim.x + threadIdx.x) >> 5);
    const int lane = threadIdx.x & 31;
    if (w >= Mrows) return;
    const int b = w / Npt;
    const int n = w - b * Npt;

    const float4* xr = (const float4*)(x3 + (size_t)w * Cdim);
    const float4 xa = xr[2 * lane];
    const float4 xb = xr[2 * lane + 1];

    const int idx_l = (lane < Kn) ? knn[n * Kn + lane] : 0;

    float alph[3];
#pragma unroll
    for (int i = 0; i < 3; ++i) alph[i] = g_alpha[(size_t)w * 3 + i];

    float acc[8] = {0.f, 0.f, 0.f, 0.f, 0.f, 0.f, 0.f, 0.f};

    for (int i = 0; i < 3; ++i) {
        const float4* qr = (const float4*)(g_Q + ((size_t)i * Mrows + w) * Cdim);
        const float4 qa = qr[2 * lane];
        const float4 qb = qr[2 * lane + 1];
        const __half* Kbase = g_K + ((size_t)i * Mrows + (size_t)b * Npt) * Cdim;
        const __half* Vbase = g_V + ((size_t)i * Mrows + (size_t)b * Npt) * Cdim;

        float s[Kn];
#pragma unroll
        for (int k = 0; k < Kn; ++k) {
            const int j = __shfl_sync(FULLMASK, idx_l, k);
            const uint4 kv = *(const uint4*)(Kbase + (size_t)j * Cdim + lane * 8);
            s[k] = wsum(dot8h(qa, qb, kv)) * 0.0625f;   // 1/sqrt(256)
        }
        float m = s[0];
#pragma unroll
        for (int k = 1; k < Kn; ++k) m = fmaxf(m, s[k]);
        float ssum = 0.f;
#pragma unroll
        for (int k = 0; k < Kn; ++k) { s[k] = __expf(s[k] - m); ssum += s[k]; }
        const float sinv = 1.f / ssum;

        float o[8] = {0.f, 0.f, 0.f, 0.f, 0.f, 0.f, 0.f, 0.f};
#pragma unroll
        for (int k = 0; k < Kn; ++k) {
            const int j = __shfl_sync(FULLMASK, idx_l, k);
            const uint4 vv = *(const uint4*)(Vbase + (size_t)j * Cdim + lane * 8);
            const __half2* vh = (const __half2*)&vv;
            const float2 f0 = __half22float2(vh[0]);
            const float2 f1 = __half22float2(vh[1]);
            const float2 f2 = __half22float2(vh[2]);
            const float2 f3 = __half22float2(vh[3]);
            const float aw = s[k] * sinv;
            o[0] += aw * f0.x; o[1] += aw * f0.y; o[2] += aw * f1.x; o[3] += aw * f1.y;
            o[4] += aw * f2.x; o[5] += aw * f2.y; o[6] += aw * f3.x; o[7] += aw * f3.y;
        }
        float r[8];
        r[0] = o[0] + qa.x; r[1] = o[1] + qa.y; r[2] = o[2] + qa.z; r[3] = o[3] + qa.w;
        r[4] = o[4] + qb.x; r[5] = o[5] + qb.y; r[6] = o[6] + qb.z; r[7] = o[7] + qb.w;

        float part = 0.f;
#pragma unroll
        for (int t = 0; t < 8; ++t) part += r[t];
        const float mean = wsum(part) * (1.f / Cdim);
        float vpart = 0.f;
#pragma unroll
        for (int t = 0; t < 8; ++t) { const float d = r[t] - mean; vpart += d * d; }
        const float var  = wsum(vpart) * (1.f / Cdim);
        const float rstd = rsqrtf(var + 1e-5f);

        const float4 ga = ((const float4*)(ln_g + i * Cdim))[2 * lane];
        const float4 gb = ((const float4*)(ln_g + i * Cdim))[2 * lane + 1];
        const float4 ba = ((const float4*)(ln_b + i * Cdim))[2 * lane];
        const float4 bb = ((const float4*)(ln_b + i * Cdim))[2 * lane + 1];
        const float al = alph[i];
        acc[0] += al * ((r[0] - mean) * rstd * ga.x + ba.x);
        acc[1] += al * ((r[1] - mean) * rstd * ga.y + ba.y);
        acc[2] += al * ((r[2] - mean) * rstd * ga.z + ba.z);
        acc[3] += al * ((r[3] - mean) * rstd * ga.w + ba.w);
        acc[4] += al * ((r[4] - mean) * rstd * gb.x + bb.x);
        acc[5] += al * ((r[5] - mean) * rstd * gb.y + bb.y);
        acc[6] += al * ((r[6] - mean) * rstd * gb.z + bb.z);
        acc[7] += al * ((r[7] - mean) * rstd * gb.w + bb.w);
    }

    // final residual + LN
    float r[8];
    r[0] = acc[0] + xa.x; r[1] = acc[1] + xa.y; r[2] = acc[2] + xa.z; r[3] = acc[3] + xa.w;
    r[4] = acc[4] + xb.x; r[5] = acc[5] + xb.y; r[6] = acc[6] + xb.z; r[7] = acc[7] + xb.w;
    float part = 0.f;
#pragma unroll
    for (int t = 0; t < 8; ++t) part += r[t];
    const float mean = wsum(part) * (1.f / Cdim);
    float vpart = 0.f;
#pragma unroll
    for (int t = 0; t < 8; ++t) { const float d = r[t] - mean; vpart += d * d; }
    const float var  = wsum(vpart) * (1.f / Cdim);
    const float rstd = rsqrtf(var + 1e-5f);

    const float4 ga = ((const float4*)fn_g)[2 * lane];
    const float4 gb = ((const float4*)fn_g)[2 * lane + 1];
    const float4 ba = ((const float4*)fn_b)[2 * lane];
    const float4 bb = ((const float4*)fn_b)[2 * lane + 1];

    float4 oa, ob;
    oa.x = (r[0] - mean) * rstd * ga.x + ba.x;
    oa.y = (r[1] - mean) * rstd * ga.y + ba.y;
    oa.z = (r[2] - mean) * rstd * ga.z + ba.z;
    oa.w = (r[3] - mean) * rstd * ga.w + ba.w;
    ob.x = (r[4] - mean) * rstd * gb.x + bb.x;
    ob.y = (r[5] - mean) * rstd * gb.y + bb.y;
    ob.z = (r[6] - mean) * rstd * gb.z + bb.z;
    ob.w = (r[7] - mean) * rstd * gb.w + bb.w;

    float4* orow = (float4*)(out + (size_t)w * Cdim);
    orow[2 * lane]     = oa;
    orow[2 * lane + 1] = ob;
}

// --------------------------------- launch ----------------------------------
extern "C" void kernel_launch(void* const* d_in, const int* in_sizes, int n_in,
                              void* d_out, int out_size) {
    const float* x0   = (const float*)d_in[0];
    const float* x1   = (const float*)d_in[1];
    const float* x2   = (const float*)d_in[2];
    const float* x3   = (const float*)d_in[3];
    const int*   knn  = (const int*)d_in[4];
    const float* Wq   = (const float*)d_in[5];
    const float* bq   = (const float*)d_in[6];
    const float* Wk   = (const float*)d_in[7];
    const float* bk   = (const float*)d_in[8];
    const float* Wv   = (const float*)d_in[9];
    const float* bv   = (const float*)d_in[10];
    const float* ln_g = (const float*)d_in[11];
    const float* ln_b = (const float*)d_in[12];
    const float* Wg1  = (const float*)d_in[13];
    const float* bg1  = (const float*)d_in[14];
    const float* Wg2  = (const float*)d_in[15];
    const float* bg2  = (const float*)d_in[16];
    const float* fn_g = (const float*)d_in[17];
    const float* fn_b = (const float*)d_in[18];
    float* out = (float*)d_out;

    float *Qp, *Hp;
    __half *Kp, *Vp;
    cudaGetSymbolAddress((void**)&Qp, g_Q);
    cudaGetSymbolAddress((void**)&Kp, g_K);
    cudaGetSymbolAddress((void**)&Vp, g_V);
    cudaGetSymbolAddress((void**)&Hp, g_H);

    cudaFuncSetAttribute(gemm_tf32_kernel,
                         cudaFuncAttributeMaxDynamicSharedMemorySize, SMEM_BYTES);

    GemmJobs jobs;
    const float* xs[3] = {x0, x1, x2};
    const size_t S = (size_t)Mrows * Cdim;
    for (int i = 0; i < 3; ++i) {
        jobs.j[i]     = { xs[i], Wq + (size_t)i * Cdim * Cdim, bq + i * Cdim, Qp + (size_t)i * S, Cdim, 0, 0 };
        jobs.j[3 + i] = { x3,    Wk + (size_t)i * Cdim * Cdim, bk + i * Cdim, Kp + (size_t)i * S, Cdim, 0, 1 };
        jobs.j[6 + i] = { x3,    Wv + (size_t)i * Cdim * Cdim, bv + i * Cdim, Vp + (size_t)i * S, Cdim, 0, 1 };
    }
    jobs.j[9] = { x3, Wg1, bg1, Hp, Hdim, 1, 0 };

    dim3 gg((Mrows + BM - 1) / BM, Cdim / BN, 10);   // 313 x 2 x 10
    gemm_tf32_kernel<<<gg, 256, SMEM_BYTES>>>(jobs);

    const int warpsBlocks = (Mrows * 32 + 255) / 256;   // 5000
    gate_kernel<<<warpsBlocks, 256>>>(Wg2, bg2);
    attn_kernel<<<warpsBlocks, 256>>>(x3, knn, ln_g, ln_b, fn_g, fn_b, out);
}

// round 5
// speedup vs baseline: 2.5718x; 1.2034x over previous
#include <cuda_runtime.h>
#include <cuda_fp16.h>
#include <cstdint>
#include <cstddef>

#define FULLMASK 0xffffffffu

constexpr int Bx    = 2;
constexpr int Npt   = 20000;
constexpr int Cdim  = 256;
constexpr int Kn    = 16;
constexpr int Hdim  = 128;
constexpr int Mrows = Bx * Npt;   // 40000

// ---------------- scratch (device globals: allocation-free) ----------------
__device__ float  g_Q[(size_t)3 * Mrows * Cdim];
__device__ __half g_K[(size_t)3 * Mrows * Cdim];
__device__ __half g_V[(size_t)3 * Mrows * Cdim];
__device__ float  g_H[(size_t)Mrows * Hdim];
__device__ float  g_alpha[(size_t)Mrows * 3];

// ---------------- fp16 GEMM:  C[M,N] = A[M,256] @ W[N,256]^T + bias --------
struct GemmJob {
    const float* A;
    const float* W;
    const float* bias;
    void*        C;
    int          ncols;
    int          relu;
    int          half_out;
};
struct GemmJobs { GemmJob j[10]; };

constexpr int BM = 128, BN = 128, BK = 32;
constexpr int LDSH = 40;                     // halfs per row (pad): (20g+t4)%32 distinct
constexpr int KTILES = Cdim / BK;            // 8

__device__ __forceinline__ uint2 f4toh4(float4 v) {
    union { __half2 h; unsigned u; } a, b;
    a.h = __floats2half2_rn(v.x, v.y);
    b.h = __floats2half2_rn(v.z, v.w);
    return make_uint2(a.u, b.u);
}

__device__ __forceinline__ void mma16(float c[4], const unsigned a[4], const unsigned b[2]) {
    asm volatile(
        "mma.sync.aligned.m16n8k16.row.col.f32.f16.f16.f32 "
        "{%0,%1,%2,%3}, {%4,%5,%6,%7}, {%8,%9}, {%0,%1,%2,%3};\n"
        : "+f"(c[0]), "+f"(c[1]), "+f"(c[2]), "+f"(c[3])
        : "r"(a[0]), "r"(a[1]), "r"(a[2]), "r"(a[3]), "r"(b[0]), "r"(b[1]));
}

__global__ __launch_bounds__(256) void gemm_fp16_kernel(GemmJobs jobs) {
    GemmJob jb = jobs.j[blockIdx.z];
    if ((int)blockIdx.y * BN >= jb.ncols) return;

    __shared__ __half As[2][BM][LDSH];
    __shared__ __half Bs[2][BN][LDSH];

    const int tid  = threadIdx.x;
    const int lane = tid & 31;
    const int warp = tid >> 5;       // 0..7
    const int g    = lane >> 2;      // 0..7
    const int t4   = lane & 3;       // 0..3
    const int m0w  = (warp & 1) * 64;
    const int n0w  = (warp >> 1) * 32;

    const int lr = tid >> 3;         // 0..31
    const int lc = (tid & 7) * 4;    // 0,4,..,28

    const int rowBase = (int)blockIdx.x * BM;
    const float* Wb = jb.W + (size_t)blockIdx.y * BN * Cdim;

    float acc[4][4][4];
#pragma unroll
    for (int mt = 0; mt < 4; ++mt)
#pragma unroll
        for (int nt = 0; nt < 4; ++nt)
#pragma unroll
            for (int e = 0; e < 4; ++e) acc[mt][nt][e] = 0.f;

    float4 aReg[4], bReg[4];
    // prologue: ktile 0
#pragma unroll
    for (int i = 0; i < 4; ++i) {
        const int ra = min(rowBase + lr + i * 32, Mrows - 1);
        aReg[i] = *(const float4*)(jb.A + (size_t)ra * Cdim + lc);
        bReg[i] = *(const float4*)(Wb + (size_t)(lr + i * 32) * Cdim + lc);
    }
#pragma unroll
    for (int i = 0; i < 4; ++i) {
        *(uint2*)&As[0][lr + i * 32][lc] = f4toh4(aReg[i]);
        *(uint2*)&Bs[0][lr + i * 32][lc] = f4toh4(bReg[i]);
    }
    __syncthreads();

    for (int kt = 0; kt < KTILES; ++kt) {
        const int buf = kt & 1;
        if (kt + 1 < KTILES) {
            const int ko = (kt + 1) * BK;
#pragma unroll
            for (int i = 0; i < 4; ++i) {
                const int ra = min(rowBase + lr + i * 32, Mrows - 1);
                aReg[i] = *(const float4*)(jb.A + (size_t)ra * Cdim + ko + lc);
                bReg[i] = *(const float4*)(Wb + (size_t)(lr + i * 32) * Cdim + ko + lc);
            }
        }
#pragma unroll
        for (int ks = 0; ks < 2; ++ks) {
            const int k0 = ks * 16;
            unsigned afr[4][4];
#pragma unroll
            for (int mt = 0; mt < 4; ++mt) {
                const int mb = m0w + mt * 16;
                afr[mt][0] = *(const unsigned*)&As[buf][mb + g][k0 + 2 * t4];
                afr[mt][1] = *(const unsigned*)&As[buf][mb + g + 8][k0 + 2 * t4];
                afr[mt][2] = *(const unsigned*)&As[buf][mb + g][k0 + 2 * t4 + 8];
                afr[mt][3] = *(const unsigned*)&As[buf][mb + g + 8][k0 + 2 * t4 + 8];
            }
            unsigned bfr[4][2];
#pragma unroll
            for (int nt = 0; nt < 4; ++nt) {
                const int nb = n0w + nt * 8;
                bfr[nt][0] = *(const unsigned*)&Bs[buf][nb + g][k0 + 2 * t4];
                bfr[nt][1] = *(const unsigned*)&Bs[buf][nb + g][k0 + 2 * t4 + 8];
            }
#pragma unroll
            for (int mt = 0; mt < 4; ++mt)
#pragma unroll
                for (int nt = 0; nt < 4; ++nt)
                    mma16(acc[mt][nt], afr[mt], bfr[nt]);
        }
        if (kt + 1 < KTILES) {
            const int nb = buf ^ 1;
#pragma unroll
            for (int i = 0; i < 4; ++i) {
                *(uint2*)&As[nb][lr + i * 32][lc] = f4toh4(aReg[i]);
                *(uint2*)&Bs[nb][lr + i * 32][lc] = f4toh4(bReg[i]);
            }
            __syncthreads();
        }
    }

    // epilogue: bias (+relu), fp32 or fp16 store, row-guarded
    const int ldc = jb.ncols;
#pragma unroll
    for (int mt = 0; mt < 4; ++mt) {
#pragma unroll
        for (int nt = 0; nt < 4; ++nt) {
            const int row = rowBase + m0w + mt * 16 + g;
            const int col = (int)blockIdx.y * BN + n0w + nt * 8 + t4 * 2;
            const float b0 = jb.bias[col];
            const float b1 = jb.bias[col + 1];
            float v0 = acc[mt][nt][0] + b0;
            float v1 = acc[mt][nt][1] + b1;
            float v2 = acc[mt][nt][2] + b0;
            float v3 = acc[mt][nt][3] + b1;
            if (jb.relu) {
                v0 = fmaxf(v0, 0.f); v1 = fmaxf(v1, 0.f);
                v2 = fmaxf(v2, 0.f); v3 = fmaxf(v3, 0.f);
            }
            if (jb.half_out) {
                __half* C = (__half*)jb.C;
                if (row < Mrows)
                    *(__half2*)(C + (size_t)row * ldc + col) = __floats2half2_rn(v0, v1);
                if (row + 8 < Mrows)
                    *(__half2*)(C + (size_t)(row + 8) * ldc + col) = __floats2half2_rn(v2, v3);
            } else {
                float* C = (float*)jb.C;
                if (row < Mrows)
                    *(float2*)(C + (size_t)row * ldc + col) = make_float2(v0, v1);
                if (row + 8 < Mrows)
                    *(float2*)(C + (size_t)(row + 8) * ldc + col) = make_float2(v2, v3);
            }
        }
    }
}

// ---------------- gating: alpha = softmax(h @ Wg2^T + bg2) -----------------
__device__ __forceinline__ float wsum(float p) {
#pragma unroll
    for (int off = 16; off; off >>= 1) p += __shfl_xor_sync(FULLMASK, p, off);
    return p;
}

__global__ __launch_bounds__(256) void gate_kernel(const float* __restrict__ Wg2,
                                                   const float* __restrict__ bg2) {
    const int w    = (int)((blockIdx.x * blockDim.x + threadIdx.x) >> 5);
    const int lane = threadIdx.x & 31;
    if (w >= Mrows) return;

    const float4 h = ((const float4*)(g_H + (size_t)w * Hdim))[lane];
    float d[3];
#pragma unroll
    for (int i = 0; i < 3; ++i) {
        const float4 ww = ((const float4*)(Wg2 + i * Hdim))[lane];
        float p = h.x * ww.x + h.y * ww.y + h.z * ww.z + h.w * ww.w;
        d[i] = wsum(p) + bg2[i];
    }
    const float m  = fmaxf(d[0], fmaxf(d[1], d[2]));
    const float e0 = __expf(d[0] - m);
    const float e1 = __expf(d[1] - m);
    const float e2 = __expf(d[2] - m);
    const float inv = 1.f / (e0 + e1 + e2);
    if (lane == 0) {
        g_alpha[(size_t)w * 3 + 0] = e0 * inv;
        g_alpha[(size_t)w * 3 + 1] = e1 * inv;
        g_alpha[(size_t)w * 3 + 2] = e2 * inv;
    }
}

// ------- fused: KNN attention x3 + LN x3 + alpha combine + final LN --------
__device__ __forceinline__ float dot8h(float4 qa, float4 qb, uint4 kv) {
    const __half2* kh = (const __half2*)&kv;
    const float2 f0 = __half22float2(kh[0]);
    const float2 f1 = __half22float2(kh[1]);
    const float2 f2 = __half22float2(kh[2]);
    const float2 f3 = __half22float2(kh[3]);
    return qa.x * f0.x + qa.y * f0.y + qa.z * f1.x + qa.w * f1.y
         + qb.x * f2.x + qb.y * f2.y + qb.z * f3.x + qb.w * f3.y;
}

__global__ __launch_bounds__(256) void attn_kernel(
    const float* __restrict__ x3, const int* __restrict__ knn,
    const float* __restrict__ ln_g, const float* __restrict__ ln_b,
    const float* __restrict__ fn_g, const float* __restrict__ fn_b,
    float* __restrict__ out) {
    const int w    = (int)((blockIdx.x * blockDim.x + threadIdx.x) >> 5);
    const int lane = threadIdx.x & 31;
    if (w >= Mrows) return;
    const int b = w / Npt;
    const int n = w - b * Npt;

    const float4* xr = (const float4*)(x3 + (size_t)w * Cdim);
    const float4 xa = xr[2 * lane];
    const float4 xb = xr[2 * lane + 1];

    const int idx_l = (lane < Kn) ? knn[n * Kn + lane] : 0;

    float alph[3];
#pragma unroll
    for (int i = 0; i < 3; ++i) alph[i] = g_alpha[(size_t)w * 3 + i];

    float acc[8] = {0.f, 0.f, 0.f, 0.f, 0.f, 0.f, 0.f, 0.f};

    for (int i = 0; i < 3; ++i) {
        const float4* qr = (const float4*)(g_Q + ((size_t)i * Mrows + w) * Cdim);
        const float4 qa = qr[2 * lane];
        const float4 qb = qr[2 * lane + 1];
        const __half* Kbase = g_K + ((size_t)i * Mrows + (size_t)b * Npt) * Cdim;
        const __half* Vbase = g_V + ((size_t)i * Mrows + (size_t)b * Npt) * Cdim;

        float s[Kn];
#pragma unroll
        for (int k = 0; k < Kn; ++k) {
            const int j = __shfl_sync(FULLMASK, idx_l, k);
            const uint4 kv = *(const uint4*)(Kbase + (size_t)j * Cdim + lane * 8);
            s[k] = wsum(dot8h(qa, qb, kv)) * 0.0625f;   // 1/sqrt(256)
        }
        float m = s[0];
#pragma unroll
        for (int k = 1; k < Kn; ++k) m = fmaxf(m, s[k]);
        float ssum = 0.f;
#pragma unroll
        for (int k = 0; k < Kn; ++k) { s[k] = __expf(s[k] - m); ssum += s[k]; }
        const float sinv = 1.f / ssum;

        float o[8] = {0.f, 0.f, 0.f, 0.f, 0.f, 0.f, 0.f, 0.f};
#pragma unroll
        for (int k = 0; k < Kn; ++k) {
            const int j = __shfl_sync(FULLMASK, idx_l, k);
            const uint4 vv = *(const uint4*)(Vbase + (size_t)j * Cdim + lane * 8);
            const __half2* vh = (const __half2*)&vv;
            const float2 f0 = __half22float2(vh[0]);
            const float2 f1 = __half22float2(vh[1]);
            const float2 f2 = __half22float2(vh[2]);
            const float2 f3 = __half22float2(vh[3]);
            const float aw = s[k] * sinv;
            o[0] += aw * f0.x; o[1] += aw * f0.y; o[2] += aw * f1.x; o[3] += aw * f1.y;
            o[4] += aw * f2.x; o[5] += aw * f2.y; o[6] += aw * f3.x; o[7] += aw * f3.y;
        }
        float r[8];
        r[0] = o[0] + qa.x; r[1] = o[1] + qa.y; r[2] = o[2] + qa.z; r[3] = o[3] + qa.w;
        r[4] = o[4] + qb.x; r[5] = o[5] + qb.y; r[6] = o[6] + qb.z; r[7] = o[7] + qb.w;

        float part = 0.f;
#pragma unroll
        for (int t = 0; t < 8; ++t) part += r[t];
        const float mean = wsum(part) * (1.f / Cdim);
        float vpart = 0.f;
#pragma unroll
        for (int t = 0; t < 8; ++t) { const float d = r[t] - mean; vpart += d * d; }
        const float var  = wsum(vpart) * (1.f / Cdim);
        const float rstd = rsqrtf(var + 1e-5f);

        const float4 ga = ((const float4*)(ln_g + i * Cdim))[2 * lane];
        const float4 gb = ((const float4*)(ln_g + i * Cdim))[2 * lane + 1];
        const float4 ba = ((const float4*)(ln_b + i * Cdim))[2 * lane];
        const float4 bb = ((const float4*)(ln_b + i * Cdim))[2 * lane + 1];
        const float al = alph[i];
        acc[0] += al * ((r[0] - mean) * rstd * ga.x + ba.x);
        acc[1] += al * ((r[1] - mean) * rstd * ga.y + ba.y);
        acc[2] += al * ((r[2] - mean) * rstd * ga.z + ba.z);
        acc[3] += al * ((r[3] - mean) * rstd * ga.w + ba.w);
        acc[4] += al * ((r[4] - mean) * rstd * gb.x + bb.x);
        acc[5] += al * ((r[5] - mean) * rstd * gb.y + bb.y);
        acc[6] += al * ((r[6] - mean) * rstd * gb.z + bb.z);
        acc[7] += al * ((r[7] - mean) * rstd * gb.w + bb.w);
    }

    // final residual + LN
    float r[8];
    r[0] = acc[0] + xa.x; r[1] = acc[1] + xa.y; r[2] = acc[2] + xa.z; r[3] = acc[3] + xa.w;
    r[4] = acc[4] + xb.x; r[5] = acc[5] + xb.y; r[6] = acc[6] + xb.z; r[7] = acc[7] + xb.w;
    float part = 0.f;
#pragma unroll
    for (int t = 0; t < 8; ++t) part += r[t];
    const float mean = wsum(part) * (1.f / Cdim);
    float vpart = 0.f;
#pragma unroll
    for (int t = 0; t < 8; ++t) { const float d = r[t] - mean; vpart += d * d; }
    const float var  = wsum(vpart) * (1.f / Cdim);
    const float rstd = rsqrtf(var + 1e-5f);

    const float4 ga = ((const float4*)fn_g)[2 * lane];
    const float4 gb = ((const float4*)fn_g)[2 * lane + 1];
    const float4 ba = ((const float4*)fn_b)[2 * lane];
    const float4 bb = ((const float4*)fn_b)[2 * lane + 1];

    float4 oa, ob;
    oa.x = (r[0] - mean) * rstd * ga.x + ba.x;
    oa.y = (r[1] - mean) * rstd * ga.y + ba.y;
    oa.z = (r[2] - mean) * rstd * ga.z + ba.z;
    oa.w = (r[3] - mean) * rstd * ga.w + ba.w;
    ob.x = (r[4] - mean) * rstd * gb.x + bb.x;
    ob.y = (r[5] - mean) * rstd * gb.y + bb.y;
    ob.z = (r[6] - mean) * rstd * gb.z + bb.z;
    ob.w = (r[7] - mean) * rstd * gb.w + bb.w;

    float4* orow = (float4*)(out + (size_t)w * Cdim);
    orow[2 * lane]     = oa;
    orow[2 * lane + 1] = ob;
}

// --------------------------------- launch ----------------------------------
extern "C" void kernel_launch(void* const* d_in, const int* in_sizes, int n_in,
                              void* d_out, int out_size) {
    const float* x0   = (const float*)d_in[0];
    const float* x1   = (const float*)d_in[1];
    const float* x2   = (const float*)d_in[2];
    const float* x3   = (const float*)d_in[3];
    const int*   knn  = (const int*)d_in[4];
    const float* Wq   = (const float*)d_in[5];
    const float* bq   = (const float*)d_in[6];
    const float* Wk   = (const float*)d_in[7];
    const float* bk   = (const float*)d_in[8];
    const float* Wv   = (const float*)d_in[9];
    const float* bv   = (const float*)d_in[10];
    const float* ln_g = (const float*)d_in[11];
    const float* ln_b = (const float*)d_in[12];
    const float* Wg1  = (const float*)d_in[13];
    const float* bg1  = (const float*)d_in[14];
    const float* Wg2  = (const float*)d_in[15];
    const float* bg2  = (const float*)d_in[16];
    const float* fn_g = (const float*)d_in[17];
    const float* fn_b = (const float*)d_in[18];
    float* out = (float*)d_out;

    float *Qp, *Hp;
    __half *Kp, *Vp;
    cudaGetSymbolAddress((void**)&Qp, g_Q);
    cudaGetSymbolAddress((void**)&Kp, g_K);
    cudaGetSymbolAddress((void**)&Vp, g_V);
    cudaGetSymbolAddress((void**)&Hp, g_H);

    GemmJobs jobs;
    const float* xs[3] = {x0, x1, x2};
    const size_t S = (size_t)Mrows * Cdim;
    for (int i = 0; i < 3; ++i) {
        jobs.j[i]     = { xs[i], Wq + (size_t)i * Cdim * Cdim, bq + i * Cdim, Qp + (size_t)i * S, Cdim, 0, 0 };
        jobs.j[3 + i] = { x3,    Wk + (size_t)i * Cdim * Cdim, bk + i * Cdim, Kp + (size_t)i * S, Cdim, 0, 1 };
        jobs.j[6 + i] = { x3,    Wv + (size_t)i * Cdim * Cdim, bv + i * Cdim, Vp + (size_t)i * S, Cdim, 0, 1 };
    }
    jobs.j[9] = { x3, Wg1, bg1, Hp, Hdim, 1, 0 };

    dim3 gg((Mrows + BM - 1) / BM, Cdim / BN, 10);   // 313 x 2 x 10
    gemm_fp16_kernel<<<gg, 256>>>(jobs);

    const int warpsBlocks = (Mrows * 32 + 255) / 256;   // 5000
    gate_kernel<<<warpsBlocks, 256>>>(Wg2, bg2);
    attn_kernel<<<warpsBlocks, 256>>>(x3, knn, ln_g, ln_b, fn_g, fn_b, out);
}

// round 6
// speedup vs baseline: 2.7968x; 1.0875x over previous
#include <cuda_runtime.h>
#include <cuda_fp16.h>
#include <cstdint>
#include <cstddef>

#define FULLMASK 0xffffffffu

constexpr int Bx    = 2;
constexpr int Npt   = 20000;
constexpr int Cdim  = 256;
constexpr int Kn    = 16;
constexpr int Hdim  = 128;
constexpr int Mrows = Bx * Npt;   // 40000

// ---------------- scratch (device globals: allocation-free) ----------------
__device__ float  g_Q[(size_t)3 * Mrows * Cdim];
__device__ __half g_K[(size_t)3 * Mrows * Cdim];
__device__ __half g_V[(size_t)3 * Mrows * Cdim];
__device__ float  g_H[(size_t)Mrows * Hdim];
__device__ float  g_alpha[(size_t)Mrows * 3];

// ---------------- fp16 GEMM (B-resident persistent + ldmatrix) ------------
struct GemmJob {
    const float* A;
    const float* W;
    const float* bias;
    void*        C;
    int          ncols;
    int          relu;
    int          half_out;
};
struct GemmJobs { GemmJob j[10]; };

constexpr int BM = 128;               // M tile
constexpr int BK = 32;                // k chunk
constexpr int KTILES = Cdim / BK;     // 8
constexpr int LDSA = 40;              // A smem stride (halfs): 80B rows, LDSM conflict-free
constexpr int LDSB = 264;             // B smem stride (halfs): 528B rows, LDSM conflict-free
constexpr int WORKERS = 31;
constexpr int MTILES = (Mrows + BM - 1) / BM;   // 313

// dynamic smem carve
constexpr int SMB_OFF = 0;
constexpr int SMB_BYTES = 128 * LDSB * 2;          // 67584
constexpr int SMA_OFF = SMB_BYTES;
constexpr int SMA_BYTES = 2 * BM * LDSA * 2;       // 20480
constexpr int SM_TOT = SMA_OFF + SMA_BYTES;        // 88064

__device__ __forceinline__ uint32_t smem_u32(const void* p) {
    uint32_t a;
    asm("{ .reg .u64 t; cvta.to.shared.u64 t, %1; cvt.u32.u64 %0, t; }" : "=r"(a) : "l"(p));
    return a;
}
__device__ __forceinline__ uint2 f4toh4(float4 v) {
    union { __half2 h; unsigned u; } a, b;
    a.h = __floats2half2_rn(v.x, v.y);
    b.h = __floats2half2_rn(v.z, v.w);
    return make_uint2(a.u, b.u);
}
__device__ __forceinline__ void ldsm4(unsigned r[4], uint32_t addr) {
    asm volatile("ldmatrix.sync.aligned.m8n8.x4.shared.b16 {%0,%1,%2,%3}, [%4];"
        : "=r"(r[0]), "=r"(r[1]), "=r"(r[2]), "=r"(r[3]) : "r"(addr));
}
__device__ __forceinline__ void mma16(float c[4], const unsigned a[4], const unsigned b[2]) {
    asm volatile(
        "mma.sync.aligned.m16n8k16.row.col.f32.f16.f16.f32 "
        "{%0,%1,%2,%3}, {%4,%5,%6,%7}, {%8,%9}, {%0,%1,%2,%3};\n"
        : "+f"(c[0]), "+f"(c[1]), "+f"(c[2]), "+f"(c[3])
        : "r"(a[0]), "r"(a[1]), "r"(a[2]), "r"(a[3]), "r"(b[0]), "r"(b[1]));
}

__global__ __launch_bounds__(256, 2) void gemm_fp16_kernel(GemmJobs jobs) {
    GemmJob jb = jobs.j[blockIdx.z];
    const int yoff = (int)blockIdx.y * 128;
    if (yoff >= jb.ncols) return;

    extern __shared__ char sm[];
    __half* Bres = (__half*)(sm + SMB_OFF);
    __half* Asm  = (__half*)(sm + SMA_OFF);   // [2][BM][LDSA]

    const int tid  = threadIdx.x;
    const int lane = tid & 31;
    const int warp = tid >> 5;       // 0..7
    const int g    = lane >> 2;      // 0..7
    const int t4   = lane & 3;       // 0..3
    const int m0w  = (warp & 1) * 64;
    const int n0w  = (warp >> 1) * 32;

    const int lr = tid >> 3;         // 0..31 (A staging row)
    const int lc = (tid & 7) * 4;    // 0,4,..,28

    // ldmatrix per-lane address components
    const int rowA = lane & 15;
    const int kA8  = (lane >> 4) * 8;
    const int rowB = (lane & 7) + ((lane >> 4) << 3);
    const int kB8  = ((lane >> 3) & 1) << 3;

    const uint32_t sA = smem_u32(Asm);
    const uint32_t sB = smem_u32(Bres);

    // ---- load resident B half (128 cols of this job) as fp16, once ----
    for (int idx = tid; idx < 128 * 64; idx += 256) {
        const int r  = idx >> 6;
        const int c4 = (idx & 63) * 4;
        const float4 v = *(const float4*)(jb.W + (size_t)(yoff + r) * Cdim + c4);
        *(uint2*)&Bres[r * LDSB + c4] = f4toh4(v);
    }
    __syncthreads();

    const int ldc = jb.ncols;

    for (int mt = (int)blockIdx.x; mt < MTILES; mt += WORKERS) {
        const int rowBase = mt * BM;

        // prologue: stage chunk 0 into buf 0
#pragma unroll
        for (int i = 0; i < 4; ++i) {
            const int ra = min(rowBase + lr + i * 32, Mrows - 1);
            const float4 v = *(const float4*)(jb.A + (size_t)ra * Cdim + lc);
            *(uint2*)&Asm[(0 * BM + lr + i * 32) * LDSA + lc] = f4toh4(v);
        }
        __syncthreads();

        float acc[4][4][4];
#pragma unroll
        for (int mtile = 0; mtile < 4; ++mtile)
#pragma unroll
            for (int nt = 0; nt < 4; ++nt)
#pragma unroll
                for (int e = 0; e < 4; ++e) acc[mtile][nt][e] = 0.f;

        for (int kt = 0; kt < KTILES; ++kt) {
            const int buf = kt & 1;
            float4 aReg[4];
            if (kt + 1 < KTILES) {
                const int ko = (kt + 1) * BK;
#pragma unroll
                for (int i = 0; i < 4; ++i) {
                    const int ra = min(rowBase + lr + i * 32, Mrows - 1);
                    aReg[i] = *(const float4*)(jb.A + (size_t)ra * Cdim + ko + lc);
                }
            }
#pragma unroll
            for (int ks = 0; ks < 2; ++ks) {
                const int kloc = ks * 16;            // within A chunk
                const int kglb = kt * BK + kloc;     // within resident B
                unsigned afr[4][4];
#pragma unroll
                for (int mtile = 0; mtile < 4; ++mtile) {
                    const uint32_t addr = sA +
                        (uint32_t)(((buf * BM) + m0w + mtile * 16 + rowA) * LDSA + kloc + kA8) * 2;
                    ldsm4(afr[mtile], addr);
                }
                unsigned bfr[4][2];
#pragma unroll
                for (int ntp = 0; ntp < 2; ++ntp) {
                    unsigned q[4];
                    const uint32_t addr = sB +
                        (uint32_t)((n0w + ntp * 16 + rowB) * LDSB + kglb + kB8) * 2;
                    ldsm4(q, addr);
                    bfr[2 * ntp][0]     = q[0];
                    bfr[2 * ntp][1]     = q[1];
                    bfr[2 * ntp + 1][0] = q[2];
                    bfr[2 * ntp + 1][1] = q[3];
                }
#pragma unroll
                for (int mtile = 0; mtile < 4; ++mtile)
#pragma unroll
                    for (int nt = 0; nt < 4; ++nt)
                        mma16(acc[mtile][nt], afr[mtile], bfr[nt]);
            }
            if (kt + 1 < KTILES) {
                const int nb = buf ^ 1;
#pragma unroll
                for (int i = 0; i < 4; ++i)
                    *(uint2*)&Asm[(nb * BM + lr + i * 32) * LDSA + lc] = f4toh4(aReg[i]);
                __syncthreads();
            }
        }

        // epilogue: bias (+relu), fp32/fp16 store, row-guarded
#pragma unroll
        for (int mtile = 0; mtile < 4; ++mtile) {
#pragma unroll
            for (int nt = 0; nt < 4; ++nt) {
                const int row = rowBase + m0w + mtile * 16 + g;
                const int col = yoff + n0w + nt * 8 + t4 * 2;
                const float b0 = jb.bias[col];
                const float b1 = jb.bias[col + 1];
                float v0 = acc[mtile][nt][0] + b0;
                float v1 = acc[mtile][nt][1] + b1;
                float v2 = acc[mtile][nt][2] + b0;
                float v3 = acc[mtile][nt][3] + b1;
                if (jb.relu) {
                    v0 = fmaxf(v0, 0.f); v1 = fmaxf(v1, 0.f);
                    v2 = fmaxf(v2, 0.f); v3 = fmaxf(v3, 0.f);
                }
                if (jb.half_out) {
                    __half* C = (__half*)jb.C;
                    if (row < Mrows)
                        *(__half2*)(C + (size_t)row * ldc + col) = __floats2half2_rn(v0, v1);
                    if (row + 8 < Mrows)
                        *(__half2*)(C + (size_t)(row + 8) * ldc + col) = __floats2half2_rn(v2, v3);
                } else {
                    float* C = (float*)jb.C;
                    if (row < Mrows)
                        *(float2*)(C + (size_t)row * ldc + col) = make_float2(v0, v1);
                    if (row + 8 < Mrows)
                        *(float2*)(C + (size_t)(row + 8) * ldc + col) = make_float2(v2, v3);
                }
            }
        }
        __syncthreads();   // all reads of A buffers done before next tile's prologue STS
    }
}

// ---------------- gating: alpha = softmax(h @ Wg2^T + bg2) -----------------
__device__ __forceinline__ float wsum(float p) {
#pragma unroll
    for (int off = 16; off; off >>= 1) p += __shfl_xor_sync(FULLMASK, p, off);
    return p;
}

__global__ __launch_bounds__(256) void gate_kernel(const float* __restrict__ Wg2,
                                                   const float* __restrict__ bg2) {
    const int w    = (int)((blockIdx.x * blockDim.x + threadIdx.x) >> 5);
    const int lane = threadIdx.x & 31;
    if (w >= Mrows) return;

    const float4 h = ((const float4*)(g_H + (size_t)w * Hdim))[lane];
    float d[3];
#pragma unroll
    for (int i = 0; i < 3; ++i) {
        const float4 ww = ((const float4*)(Wg2 + i * Hdim))[lane];
        float p = h.x * ww.x + h.y * ww.y + h.z * ww.z + h.w * ww.w;
        d[i] = wsum(p) + bg2[i];
    }
    const float m  = fmaxf(d[0], fmaxf(d[1], d[2]));
    const float e0 = __expf(d[0] - m);
    const float e1 = __expf(d[1] - m);
    const float e2 = __expf(d[2] - m);
    const float inv = 1.f / (e0 + e1 + e2);
    if (lane == 0) {
        g_alpha[(size_t)w * 3 + 0] = e0 * inv;
        g_alpha[(size_t)w * 3 + 1] = e1 * inv;
        g_alpha[(size_t)w * 3 + 2] = e2 * inv;
    }
}

// ------- fused: KNN attention x3 + LN x3 + alpha combine + final LN --------
__device__ __forceinline__ float dot8h(float4 qa, float4 qb, uint4 kv) {
    const __half2* kh = (const __half2*)&kv;
    const float2 f0 = __half22float2(kh[0]);
    const float2 f1 = __half22float2(kh[1]);
    const float2 f2 = __half22float2(kh[2]);
    const float2 f3 = __half22float2(kh[3]);
    return qa.x * f0.x + qa.y * f0.y + qa.z * f1.x + qa.w * f1.y
         + qb.x * f2.x + qb.y * f2.y + qb.z * f3.x + qb.w * f3.y;
}

__global__ __launch_bounds__(256) void attn_kernel(
    const float* __restrict__ x3, const int* __restrict__ knn,
    const float* __restrict__ ln_g, const float* __restrict__ ln_b,
    const float* __restrict__ fn_g, const float* __restrict__ fn_b,
    float* __restrict__ out) {
    const int w    = (int)((blockIdx.x * blockDim.x + threadIdx.x) >> 5);
    const int lane = threadIdx.x & 31;
    if (w >= Mrows) return;
    const int b = w / Npt;
    const int n = w - b * Npt;

    const float4* xr = (const float4*)(x3 + (size_t)w * Cdim);
    const float4 xa = xr[2 * lane];
    const float4 xb = xr[2 * lane + 1];

    const int idx_l = (lane < Kn) ? knn[n * Kn + lane] : 0;

    float alph[3];
#pragma unroll
    for (int i = 0; i < 3; ++i) alph[i] = g_alpha[(size_t)w * 3 + i];

    float acc[8] = {0.f, 0.f, 0.f, 0.f, 0.f, 0.f, 0.f, 0.f};

    for (int i = 0; i < 3; ++i) {
        const float4* qr = (const float4*)(g_Q + ((size_t)i * Mrows + w) * Cdim);
        const float4 qa = qr[2 * lane];
        const float4 qb = qr[2 * lane + 1];
        const __half* Kbase = g_K + ((size_t)i * Mrows + (size_t)b * Npt) * Cdim;
        const __half* Vbase = g_V + ((size_t)i * Mrows + (size_t)b * Npt) * Cdim;

        float s[Kn];
#pragma unroll
        for (int k = 0; k < Kn; ++k) {
            const int j = __shfl_sync(FULLMASK, idx_l, k);
            const uint4 kv = *(const uint4*)(Kbase + (size_t)j * Cdim + lane * 8);
            s[k] = wsum(dot8h(qa, qb, kv)) * 0.0625f;   // 1/sqrt(256)
        }
        float m = s[0];
#pragma unroll
        for (int k = 1; k < Kn; ++k) m = fmaxf(m, s[k]);
        float ssum = 0.f;
#pragma unroll
        for (int k = 0; k < Kn; ++k) { s[k] = __expf(s[k] - m); ssum += s[k]; }
        const float sinv = 1.f / ssum;

        float o[8] = {0.f, 0.f, 0.f, 0.f, 0.f, 0.f, 0.f, 0.f};
#pragma unroll
        for (int k = 0; k < Kn; ++k) {
            const int j = __shfl_sync(FULLMASK, idx_l, k);
            const uint4 vv = *(const uint4*)(Vbase + (size_t)j * Cdim + lane * 8);
            const __half2* vh = (const __half2*)&vv;
            const float2 f0 = __half22float2(vh[0]);
            const float2 f1 = __half22float2(vh[1]);
            const float2 f2 = __half22float2(vh[2]);
            const float2 f3 = __half22float2(vh[3]);
            const float aw = s[k] * sinv;
            o[0] += aw * f0.x; o[1] += aw * f0.y; o[2] += aw * f1.x; o[3] += aw * f1.y;
            o[4] += aw * f2.x; o[5] += aw * f2.y; o[6] += aw * f3.x; o[7] += aw * f3.y;
        }
        float r[8];
        r[0] = o[0] + qa.x; r[1] = o[1] + qa.y; r[2] = o[2] + qa.z; r[3] = o[3] + qa.w;
        r[4] = o[4] + qb.x; r[5] = o[5] + qb.y; r[6] = o[6] + qb.z; r[7] = o[7] + qb.w;

        float part = 0.f;
#pragma unroll
        for (int t = 0; t < 8; ++t) part += r[t];
        const float mean = wsum(part) * (1.f / Cdim);
        float vpart = 0.f;
#pragma unroll
        for (int t = 0; t < 8; ++t) { const float d = r[t] - mean; vpart += d * d; }
        const float var  = wsum(vpart) * (1.f / Cdim);
        const float rstd = rsqrtf(var + 1e-5f);

        const float4 ga = ((const float4*)(ln_g + i * Cdim))[2 * lane];
        const float4 gb = ((const float4*)(ln_g + i * Cdim))[2 * lane + 1];
        const float4 ba = ((const float4*)(ln_b + i * Cdim))[2 * lane];
        const float4 bb = ((const float4*)(ln_b + i * Cdim))[2 * lane + 1];
        const float al = alph[i];
        acc[0] += al * ((r[0] - mean) * rstd * ga.x + ba.x);
        acc[1] += al * ((r[1] - mean) * rstd * ga.y + ba.y);
        acc[2] += al * ((r[2] - mean) * rstd * ga.z + ba.z);
        acc[3] += al * ((r[3] - mean) * rstd * ga.w + ba.w);
        acc[4] += al * ((r[4] - mean) * rstd * gb.x + bb.x);
        acc[5] += al * ((r[5] - mean) * rstd * gb.y + bb.y);
        acc[6] += al * ((r[6] - mean) * rstd * gb.z + bb.z);
        acc[7] += al * ((r[7] - mean) * rstd * gb.w + bb.w);
    }

    // final residual + LN
    float r[8];
    r[0] = acc[0] + xa.x; r[1] = acc[1] + xa.y; r[2] = acc[2] + xa.z; r[3] = acc[3] + xa.w;
    r[4] = acc[4] + xb.x; r[5] = acc[5] + xb.y; r[6] = acc[6] + xb.z; r[7] = acc[7] + xb.w;
    float part = 0.f;
#pragma unroll
    for (int t = 0; t < 8; ++t) part += r[t];
    const float mean = wsum(part) * (1.f / Cdim);
    float vpart = 0.f;
#pragma unroll
    for (int t = 0; t < 8; ++t) { const float d = r[t] - mean; vpart += d * d; }
    const float var  = wsum(vpart) * (1.f / Cdim);
    const float rstd = rsqrtf(var + 1e-5f);

    const float4 ga = ((const float4*)fn_g)[2 * lane];
    const float4 gb = ((const float4*)fn_g)[2 * lane + 1];
    const float4 ba = ((const float4*)fn_b)[2 * lane];
    const float4 bb = ((const float4*)fn_b)[2 * lane + 1];

    float4 oa, ob;
    oa.x = (r[0] - mean) * rstd * ga.x + ba.x;
    oa.y = (r[1] - mean) * rstd * ga.y + ba.y;
    oa.z = (r[2] - mean) * rstd * ga.z + ba.z;
    oa.w = (r[3] - mean) * rstd * ga.w + ba.w;
    ob.x = (r[4] - mean) * rstd * gb.x + bb.x;
    ob.y = (r[5] - mean) * rstd * gb.y + bb.y;
    ob.z = (r[6] - mean) * rstd * gb.z + bb.z;
    ob.w = (r[7] - mean) * rstd * gb.w + bb.w;

    float4* orow = (float4*)(out + (size_t)w * Cdim);
    orow[2 * lane]     = oa;
    orow[2 * lane + 1] = ob;
}

// --------------------------------- launch ----------------------------------
extern "C" void kernel_launch(void* const* d_in, const int* in_sizes, int n_in,
                              void* d_out, int out_size) {
    const float* x0   = (const float*)d_in[0];
    const float* x1   = (const float*)d_in[1];
    const float* x2   = (const float*)d_in[2];
    const float* x3   = (const float*)d_in[3];
    const int*   knn  = (const int*)d_in[4];
    const float* Wq   = (const float*)d_in[5];
    const float* bq   = (const float*)d_in[6];
    const float* Wk   = (const float*)d_in[7];
    const float* bk   = (const float*)d_in[8];
    const float* Wv   = (const float*)d_in[9];
    const float* bv   = (const float*)d_in[10];
    const float* ln_g = (const float*)d_in[11];
    const float* ln_b = (const float*)d_in[12];
    const float* Wg1  = (const float*)d_in[13];
    const float* bg1  = (const float*)d_in[14];
    const float* Wg2  = (const float*)d_in[15];
    const float* bg2  = (const float*)d_in[16];
    const float* fn_g = (const float*)d_in[17];
    const float* fn_b = (const float*)d_in[18];
    float* out = (float*)d_out;

    float *Qp, *Hp;
    __half *Kp, *Vp;
    cudaGetSymbolAddress((void**)&Qp, g_Q);
    cudaGetSymbolAddress((void**)&Kp, g_K);
    cudaGetSymbolAddress((void**)&Vp, g_V);
    cudaGetSymbolAddress((void**)&Hp, g_H);

    cudaFuncSetAttribute(gemm_fp16_kernel,
                         cudaFuncAttributeMaxDynamicSharedMemorySize, SM_TOT);

    GemmJobs jobs;
    const float* xs[3] = {x0, x1, x2};
    const size_t S = (size_t)Mrows * Cdim;
    for (int i = 0; i < 3; ++i) {
        jobs.j[i]     = { xs[i], Wq + (size_t)i * Cdim * Cdim, bq + i * Cdim, Qp + (size_t)i * S, Cdim, 0, 0 };
        jobs.j[3 + i] = { x3,    Wk + (size_t)i * Cdim * Cdim, bk + i * Cdim, Kp + (size_t)i * S, Cdim, 0, 1 };
        jobs.j[6 + i] = { x3,    Wv + (size_t)i * Cdim * Cdim, bv + i * Cdim, Vp + (size_t)i * S, Cdim, 0, 1 };
    }
    jobs.j[9] = { x3, Wg1, bg1, Hp, Hdim, 1, 0 };

    dim3 gg(WORKERS, 2, 10);   // 31 x 2 x 10 persistent-ish workers
    gemm_fp16_kernel<<<gg, 256, SM_TOT>>>(jobs);

    const int warpsBlocks = (Mrows * 32 + 255) / 256;   // 5000
    gate_kernel<<<warpsBlocks, 256>>>(Wg2, bg2);
    attn_kernel<<<warpsBlocks, 256>>>(x3, knn, ln_g, ln_b, fn_g, fn_b, out);
}